// round 1
// baseline (speedup 1.0000x reference)
#include <cuda_runtime.h>
#include <math.h>

// Problem constants (fixed by the reference)
constexpr int Nn = 100000;
constexpr int Ee = 1600000;

// Scratch (static __device__ arrays: allocation-free per harness rules)
__device__ float d_node[Nn * 64];     // current node features
__device__ float d_agg[Nn * 64];      // aggregation buffer / MLP temp
__device__ float d_norm[Ee];          // edge weight -> edge norm (in place)
__device__ float d_dis[Nn];           // degree -> deg^-0.5 (in place)
__device__ float d_selfnorm[Nn];      // dis[i]^2 (self-loop norm)

__device__ __forceinline__ float leaky(float v, float s) {
    return v > 0.0f ? v : s * v;
}

// ---------------------------------------------------------------------------
// deg init: self-loop contributes weight 1.0 to every node's degree
__global__ void init_deg_kernel() {
    int i = blockIdx.x * blockDim.x + threadIdx.x;
    if (i < Nn) d_dis[i] = 1.0f;
}

// ---------------------------------------------------------------------------
// Edge MLP: ea[E,4] -> leaky(@We1[4,16]+be1,0.2) -> leaky(@We2[16,1]+be2,0.005)
// Writes ew into d_norm[e]; accumulates deg[col] += ew (spread atomics).
__global__ void edge_kernel(const float4* __restrict__ ea,
                            const int* __restrict__ ei,
                            const float* __restrict__ W1,
                            const float* __restrict__ b1,
                            const float* __restrict__ W2,
                            const float* __restrict__ b2) {
    __shared__ float sW1[64];
    __shared__ float sb1[16];
    __shared__ float sW2[16];
    __shared__ float sb2;
    int t = threadIdx.x;
    if (t < 64) sW1[t] = W1[t];
    if (t < 16) sb1[t] = b1[t];
    if (t >= 64 && t < 80) sW2[t - 64] = W2[t - 64];
    if (t == 80) sb2 = b2[0];
    __syncthreads();

    int e = blockIdx.x * blockDim.x + t;
    if (e >= Ee) return;
    float4 a = ea[e];
    float a0 = isnan(a.x) ? 0.0f : a.x;
    float a1 = isnan(a.y) ? 0.0f : a.y;
    float a2 = isnan(a.z) ? 0.0f : a.z;
    float a3 = isnan(a.w) ? 0.0f : a.w;

    float s = sb2;
#pragma unroll
    for (int j = 0; j < 16; j++) {
        float v = a0 * sW1[j] + a1 * sW1[16 + j] + a2 * sW1[32 + j] +
                  a3 * sW1[48 + j] + sb1[j];
        v = leaky(v, 0.2f);
        s += v * sW2[j];
    }
    float ew = leaky(s, 0.005f);
    d_norm[e] = ew;
    atomicAdd(&d_dis[ei[Ee + e]], ew);
}

// ---------------------------------------------------------------------------
// dis = deg^-0.5 (inf -> 0, NaN for deg<0 matches reference); selfnorm = dis^2
__global__ void dis_kernel() {
    int i = blockIdx.x * blockDim.x + threadIdx.x;
    if (i >= Nn) return;
    float d = d_dis[i];
    float r = rsqrtf(d);
    if (isinf(r)) r = 0.0f;
    d_dis[i] = r;
    d_selfnorm[i] = r * r;
}

// ---------------------------------------------------------------------------
// norm[e] = dis[row] * ew[e] * dis[col]  (in place on d_norm)
__global__ void norm_kernel(const int* __restrict__ ei) {
    int e = blockIdx.x * blockDim.x + threadIdx.x;
    if (e >= Ee) return;
    int row = ei[e];
    int col = ei[Ee + e];
    d_norm[e] = d_dis[row] * d_norm[e] * d_dis[col];
}

// ---------------------------------------------------------------------------
// Node MLP stage 1: x[N,7] -> leaky(@Wn1[7,64]+bn1, 0.2) -> d_agg (as temp)
__global__ void node1_kernel(const float* __restrict__ x,
                             const float* __restrict__ W1,
                             const float* __restrict__ b1) {
    __shared__ float sW[7 * 64];
    __shared__ float sb[64];
    for (int i = threadIdx.x; i < 448; i += blockDim.x) sW[i] = W1[i];
    if (threadIdx.x < 64) sb[threadIdx.x] = b1[threadIdx.x];
    __syncthreads();

    int r = blockIdx.x * blockDim.x + threadIdx.x;
    if (r >= Nn) return;
    float xi[7];
#pragma unroll
    for (int i = 0; i < 7; i++) {
        float v = x[r * 7 + i];
        xi[i] = isnan(v) ? 0.0f : v;
    }
    float4* outp = reinterpret_cast<float4*>(d_agg) + (size_t)r * 16;
#pragma unroll
    for (int j4 = 0; j4 < 16; j4++) {
        float o[4];
#pragma unroll
        for (int c = 0; c < 4; c++) {
            int j = j4 * 4 + c;
            float v = sb[j];
#pragma unroll
            for (int i = 0; i < 7; i++) v += xi[i] * sW[i * 64 + j];
            o[c] = leaky(v, 0.2f);
        }
        outp[j4] = make_float4(o[0], o[1], o[2], o[3]);
    }
}

// ---------------------------------------------------------------------------
// 64x64 GEMM + bias + leaky, one row per thread, W broadcast from smem.
// IN_AGG: in = d_agg, out = d_node (else in = d_node, out = d_agg).
// SELFINIT: additionally write d_agg[r] = out[r] * selfnorm[r]  (self-loop
// pre-initialization of the next layer's aggregation buffer). Only valid with
// IN_AGG=true; per-thread row-local, all reads precede writes -> in-place safe.
template <bool IN_AGG, bool SELFINIT>
__global__ void __launch_bounds__(256) gemm64_kernel(const float* __restrict__ W,
                                                     const float* __restrict__ b,
                                                     float slope) {
    __shared__ float sW[4096];
    __shared__ float sb[64];
    {
        const float4* W4 = reinterpret_cast<const float4*>(W);
        float4* sW4 = reinterpret_cast<float4*>(sW);
        for (int i = threadIdx.x; i < 1024; i += 256) sW4[i] = W4[i];
        if (threadIdx.x < 64) sb[threadIdx.x] = b[threadIdx.x];
    }
    __syncthreads();

    int r = blockIdx.x * 256 + threadIdx.x;
    if (r >= Nn) return;

    const float* inbase = IN_AGG ? d_agg : d_node;
    const float4* inp = reinterpret_cast<const float4*>(inbase + (size_t)r * 64);

    float acc[64];
#pragma unroll
    for (int j = 0; j < 64; j++) acc[j] = sb[j];

#pragma unroll 4
    for (int k4 = 0; k4 < 16; k4++) {
        float4 x = inp[k4];
#pragma unroll
        for (int kk = 0; kk < 4; kk++) {
            float xk = (kk == 0) ? x.x : (kk == 1) ? x.y : (kk == 2) ? x.z : x.w;
            const float4* wr =
                reinterpret_cast<const float4*>(sW + (k4 * 4 + kk) * 64);
#pragma unroll
            for (int j4 = 0; j4 < 16; j4++) {
                float4 w = wr[j4];
                acc[j4 * 4 + 0] += xk * w.x;
                acc[j4 * 4 + 1] += xk * w.y;
                acc[j4 * 4 + 2] += xk * w.z;
                acc[j4 * 4 + 3] += xk * w.w;
            }
        }
    }

    float* outbase = IN_AGG ? d_node : d_agg;
    float4* outp = reinterpret_cast<float4*>(outbase + (size_t)r * 64);
    float sn = SELFINIT ? d_selfnorm[r] : 0.0f;
    float4* agg2 = reinterpret_cast<float4*>(d_agg) + (size_t)r * 16;
#pragma unroll
    for (int j4 = 0; j4 < 16; j4++) {
        float4 o;
        o.x = leaky(acc[j4 * 4 + 0], slope);
        o.y = leaky(acc[j4 * 4 + 1], slope);
        o.z = leaky(acc[j4 * 4 + 2], slope);
        o.w = leaky(acc[j4 * 4 + 3], slope);
        outp[j4] = o;
        if (SELFINIT) {
            float4 o2 = make_float4(o.x * sn, o.y * sn, o.z * sn, o.w * sn);
            agg2[j4] = o2;
        }
    }
}

// ---------------------------------------------------------------------------
// Edge scatter: agg[col] += node[row] * norm[e].
// 16 threads per edge, float4 each; vector reduction red.global.add.v4.f32.
__global__ void scatter_kernel(const int* __restrict__ ei) {
    int t = blockIdx.x * blockDim.x + threadIdx.x;
    int e = t >> 4;
    if (e >= Ee) return;
    int j = t & 15;
    int row = __ldg(&ei[e]);
    int col = __ldg(&ei[Ee + e]);
    float n = __ldg(&d_norm[e]);
    float4 v = reinterpret_cast<const float4*>(d_node)[(size_t)row * 16 + j];
    float4* dst = reinterpret_cast<float4*>(d_agg) + (size_t)col * 16 + j;
    asm volatile("red.global.add.v4.f32 [%0], {%1, %2, %3, %4};" ::"l"(dst),
                 "f"(v.x * n), "f"(v.y * n), "f"(v.z * n), "f"(v.w * n)
                 : "memory");
}

// ---------------------------------------------------------------------------
// Final projection: node[N,64] @ Wr[64,4] + br -> out[N,4]
__global__ void final_kernel(const float* __restrict__ Wr,
                             const float* __restrict__ br,
                             float* __restrict__ out) {
    __shared__ float sW[256];
    __shared__ float sb[4];
    if (threadIdx.x < 256) sW[threadIdx.x] = Wr[threadIdx.x];
    if (threadIdx.x < 4) sb[threadIdx.x] = br[threadIdx.x];
    __syncthreads();

    int r = blockIdx.x * blockDim.x + threadIdx.x;
    if (r >= Nn) return;
    const float4* inp = reinterpret_cast<const float4*>(d_node + (size_t)r * 64);
    float acc[4] = {sb[0], sb[1], sb[2], sb[3]};
#pragma unroll
    for (int k4 = 0; k4 < 16; k4++) {
        float4 x = inp[k4];
#pragma unroll
        for (int kk = 0; kk < 4; kk++) {
            float xk = (kk == 0) ? x.x : (kk == 1) ? x.y : (kk == 2) ? x.z : x.w;
            const float* wr = sW + (k4 * 4 + kk) * 4;
            acc[0] += xk * wr[0];
            acc[1] += xk * wr[1];
            acc[2] += xk * wr[2];
            acc[3] += xk * wr[3];
        }
    }
    reinterpret_cast<float4*>(out)[r] = make_float4(acc[0], acc[1], acc[2], acc[3]);
}

// ---------------------------------------------------------------------------
extern "C" void kernel_launch(void* const* d_in, const int* in_sizes, int n_in,
                              void* d_out, int out_size) {
    const float* x = (const float*)d_in[0];
    const int* ei = (const int*)d_in[1];
    const float* ea = (const float*)d_in[2];
    const float* Wn1 = (const float*)d_in[3];
    const float* bn1 = (const float*)d_in[4];
    const float* Wn2 = (const float*)d_in[5];
    const float* bn2 = (const float*)d_in[6];
    const float* We1 = (const float*)d_in[7];
    const float* be1 = (const float*)d_in[8];
    const float* We2 = (const float*)d_in[9];
    const float* be2 = (const float*)d_in[10];
    const float* Wg = (const float*)d_in[11];
    const float* bg = (const float*)d_in[12];
    const float* Wp1 = (const float*)d_in[13];
    const float* bp1 = (const float*)d_in[14];
    const float* Wp2 = (const float*)d_in[15];
    const float* bp2 = (const float*)d_in[16];
    const float* Wr = (const float*)d_in[17];
    const float* br = (const float*)d_in[18];

    const int NB = (Nn + 255) / 256;          // 391
    const int EB = (Ee + 255) / 256;          // 6250
    const int SB = (Ee * 16 + 255) / 256;     // 100000

    // gcn_norm pipeline
    init_deg_kernel<<<NB, 256>>>();
    edge_kernel<<<EB, 256>>>((const float4*)ea, ei, We1, be1, We2, be2);
    dis_kernel<<<NB, 256>>>();
    norm_kernel<<<EB, 256>>>(ei);

    // node MLP (stage1 writes temp into d_agg; stage2 agg->node + self-init)
    node1_kernel<<<NB, 256>>>(x, Wn1, bn1);
    gemm64_kernel<true, true><<<NB, 256>>>(Wn2, bn2, 0.2f);

    // 8 GCN layers: scatter raw node features, then (agg @ Wg + bg) -> leaky,
    // with epilogue re-initializing agg for the next layer's self-loop.
    for (int i = 0; i < 8; i++) {
        scatter_kernel<<<SB, 256>>>(ei);
        gemm64_kernel<true, true><<<NB, 256>>>(Wg + i * 4096, bg + i * 64, 0.2f);
    }

    // post MLP
    gemm64_kernel<false, false><<<NB, 256>>>(Wp1, bp1, 0.2f);  // node -> agg
    gemm64_kernel<true, false><<<NB, 256>>>(Wp2, bp2, 0.2f);   // agg -> node
    final_kernel<<<NB, 256>>>(Wr, br, (float*)d_out);
}

// round 2
// speedup vs baseline: 1.4211x; 1.4211x over previous
#include <cuda_runtime.h>
#include <math.h>

constexpr int Nn = 100000;
constexpr int Ee = 1600000;
constexpr int SCAN_TILE = 1024;
constexpr int NTILES = (Nn + SCAN_TILE - 1) / SCAN_TILE;  // 98

// Scratch (static __device__ arrays: allocation-free per harness rules)
__device__ float d_node[Nn * 64];
__device__ float d_agg[Nn * 64];
__device__ float d_norm[Ee];       // edge weight -> edge norm (in place)
__device__ float d_dis[Nn];        // degree -> deg^-0.5 (in place)
__device__ float d_selfnorm[Nn];   // dis[i]^2
__device__ int d_cnt[Nn];          // in-degree counts
__device__ int d_off[Nn + 1];      // CSR offsets (exclusive scan)
__device__ int d_cur[Nn];          // running fill cursor
__device__ int d_tile[NTILES];     // scan tile sums / bases
__device__ int d_csr_src[Ee];      // CSR: source node per slot
__device__ float d_csr_w[Ee];      // CSR: norm per slot

__device__ __forceinline__ float leaky(float v, float s) {
    return v > 0.0f ? v : s * v;
}

// ---------------------------------------------------------------------------
__global__ void init_kernel() {
    int i = blockIdx.x * blockDim.x + threadIdx.x;
    if (i < Nn) { d_dis[i] = 1.0f; d_cnt[i] = 0; }
}

// ---------------------------------------------------------------------------
// Edge MLP + degree accumulation + CSR count (fused).
__global__ void edge_kernel(const float4* __restrict__ ea,
                            const int* __restrict__ ei,
                            const float* __restrict__ W1,
                            const float* __restrict__ b1,
                            const float* __restrict__ W2,
                            const float* __restrict__ b2) {
    __shared__ float sW1[64];
    __shared__ float sb1[16];
    __shared__ float sW2[16];
    __shared__ float sb2;
    int t = threadIdx.x;
    if (t < 64) sW1[t] = W1[t];
    if (t < 16) sb1[t] = b1[t];
    if (t >= 64 && t < 80) sW2[t - 64] = W2[t - 64];
    if (t == 80) sb2 = b2[0];
    __syncthreads();

    int e = blockIdx.x * blockDim.x + t;
    if (e >= Ee) return;
    float4 a = ea[e];
    float a0 = isnan(a.x) ? 0.0f : a.x;
    float a1 = isnan(a.y) ? 0.0f : a.y;
    float a2 = isnan(a.z) ? 0.0f : a.z;
    float a3 = isnan(a.w) ? 0.0f : a.w;

    float s = sb2;
#pragma unroll
    for (int j = 0; j < 16; j++) {
        float v = a0 * sW1[j] + a1 * sW1[16 + j] + a2 * sW1[32 + j] +
                  a3 * sW1[48 + j] + sb1[j];
        v = leaky(v, 0.2f);
        s += v * sW2[j];
    }
    float ew = leaky(s, 0.005f);
    d_norm[e] = ew;
    int col = ei[Ee + e];
    atomicAdd(&d_dis[col], ew);
    atomicAdd(&d_cnt[col], 1);
}

// ---------------------------------------------------------------------------
__global__ void dis_kernel() {
    int i = blockIdx.x * blockDim.x + threadIdx.x;
    if (i >= Nn) return;
    float d = d_dis[i];
    float r = rsqrtf(d);
    if (isinf(r)) r = 0.0f;
    d_dis[i] = r;
    d_selfnorm[i] = r * r;
}

// ---------------------------------------------------------------------------
__global__ void norm_kernel(const int* __restrict__ ei) {
    int e = blockIdx.x * blockDim.x + threadIdx.x;
    if (e >= Ee) return;
    d_norm[e] = d_dis[ei[e]] * d_norm[e] * d_dis[ei[Ee + e]];
}

// ---------------------------------------------------------------------------
// 3-kernel exclusive scan of d_cnt -> d_off, d_cur.
__global__ void scan1_kernel() {  // per-tile inclusive scan + tile sums
    __shared__ int sh[SCAN_TILE];
    int tid = threadIdx.x;
    int i = blockIdx.x * SCAN_TILE + tid;
    int v = (i < Nn) ? d_cnt[i] : 0;
    sh[tid] = v;
    __syncthreads();
#pragma unroll
    for (int s = 1; s < SCAN_TILE; s <<= 1) {
        int add = (tid >= s) ? sh[tid - s] : 0;
        __syncthreads();
        sh[tid] += add;
        __syncthreads();
    }
    if (i < Nn) d_off[i] = sh[tid];  // inclusive, tile-local (temp)
    if (tid == SCAN_TILE - 1) d_tile[blockIdx.x] = sh[tid];
}

__global__ void scan2_kernel() {  // exclusive scan of tile sums (1 thread)
    if (threadIdx.x == 0 && blockIdx.x == 0) {
        int run = 0;
        for (int b = 0; b < NTILES; b++) {
            int s = d_tile[b];
            d_tile[b] = run;
            run += s;
        }
        d_off[Nn] = Ee;
    }
}

__global__ void scan3_kernel() {  // finalize exclusive offsets + cursors
    int i = blockIdx.x * blockDim.x + threadIdx.x;
    if (i >= Nn) return;
    int excl = d_off[i] - d_cnt[i] + d_tile[i / SCAN_TILE];
    d_off[i] = excl;
    d_cur[i] = excl;
}

// ---------------------------------------------------------------------------
// CSR fill: slot per edge under its destination node.
__global__ void fill_kernel(const int* __restrict__ ei) {
    int e = blockIdx.x * blockDim.x + threadIdx.x;
    if (e >= Ee) return;
    int col = ei[Ee + e];
    int pos = atomicAdd(&d_cur[col], 1);
    d_csr_src[pos] = ei[e];
    d_csr_w[pos] = d_norm[e];
}

// ---------------------------------------------------------------------------
// Node MLP stage 1: x[N,7] -> leaky(@Wn1+bn1, 0.2) -> d_agg (as temp)
__global__ void node1_kernel(const float* __restrict__ x,
                             const float* __restrict__ W1,
                             const float* __restrict__ b1) {
    __shared__ float sW[7 * 64];
    __shared__ float sb[64];
    for (int i = threadIdx.x; i < 448; i += blockDim.x) sW[i] = W1[i];
    if (threadIdx.x < 64) sb[threadIdx.x] = b1[threadIdx.x];
    __syncthreads();

    int r = blockIdx.x * blockDim.x + threadIdx.x;
    if (r >= Nn) return;
    float xi[7];
#pragma unroll
    for (int i = 0; i < 7; i++) {
        float v = x[r * 7 + i];
        xi[i] = isnan(v) ? 0.0f : v;
    }
    float4* outp = reinterpret_cast<float4*>(d_agg) + (size_t)r * 16;
#pragma unroll
    for (int j4 = 0; j4 < 16; j4++) {
        float o[4];
#pragma unroll
        for (int c = 0; c < 4; c++) {
            int j = j4 * 4 + c;
            float v = sb[j];
#pragma unroll
            for (int i = 0; i < 7; i++) v += xi[i] * sW[i * 64 + j];
            o[c] = leaky(v, 0.2f);
        }
        outp[j4] = make_float4(o[0], o[1], o[2], o[3]);
    }
}

// ---------------------------------------------------------------------------
// 64x64 GEMM + bias + leaky. IN_AGG: agg->node, else node->agg.
template <bool IN_AGG>
__global__ void __launch_bounds__(256) gemm64_kernel(const float* __restrict__ W,
                                                     const float* __restrict__ b,
                                                     float slope) {
    __shared__ float sW[4096];
    __shared__ float sb[64];
    {
        const float4* W4 = reinterpret_cast<const float4*>(W);
        float4* sW4 = reinterpret_cast<float4*>(sW);
        for (int i = threadIdx.x; i < 1024; i += 256) sW4[i] = W4[i];
        if (threadIdx.x < 64) sb[threadIdx.x] = b[threadIdx.x];
    }
    __syncthreads();

    int r = blockIdx.x * 256 + threadIdx.x;
    if (r >= Nn) return;

    const float* inbase = IN_AGG ? d_agg : d_node;
    const float4* inp = reinterpret_cast<const float4*>(inbase + (size_t)r * 64);

    float acc[64];
#pragma unroll
    for (int j = 0; j < 64; j++) acc[j] = sb[j];

#pragma unroll 4
    for (int k4 = 0; k4 < 16; k4++) {
        float4 x = inp[k4];
#pragma unroll
        for (int kk = 0; kk < 4; kk++) {
            float xk = (kk == 0) ? x.x : (kk == 1) ? x.y : (kk == 2) ? x.z : x.w;
            const float4* wr =
                reinterpret_cast<const float4*>(sW + (k4 * 4 + kk) * 64);
#pragma unroll
            for (int j4 = 0; j4 < 16; j4++) {
                float4 w = wr[j4];
                acc[j4 * 4 + 0] += xk * w.x;
                acc[j4 * 4 + 1] += xk * w.y;
                acc[j4 * 4 + 2] += xk * w.z;
                acc[j4 * 4 + 3] += xk * w.w;
            }
        }
    }

    float* outbase = IN_AGG ? d_node : d_agg;
    float4* outp = reinterpret_cast<float4*>(outbase + (size_t)r * 64);
#pragma unroll
    for (int j4 = 0; j4 < 16; j4++) {
        float4 o;
        o.x = leaky(acc[j4 * 4 + 0], slope);
        o.y = leaky(acc[j4 * 4 + 1], slope);
        o.z = leaky(acc[j4 * 4 + 2], slope);
        o.w = leaky(acc[j4 * 4 + 3], slope);
        outp[j4] = o;
    }
}

// ---------------------------------------------------------------------------
// CSR gather: one warp per destination node, float2 per lane (64 feats).
// acc init = self-loop term node[n]*selfnorm[n]; then sum in-edges.
__global__ void __launch_bounds__(256) gather_kernel() {
    int warp = (blockIdx.x * blockDim.x + threadIdx.x) >> 5;
    if (warp >= Nn) return;
    int lane = threadIdx.x & 31;

    const float2* nd = reinterpret_cast<const float2*>(d_node);
    float sn = d_selfnorm[warp];
    float2 self = nd[(size_t)warp * 32 + lane];
    float accx = self.x * sn, accy = self.y * sn;

    int i = d_off[warp];
    int end = d_off[warp + 1];

    for (; i + 4 <= end; i += 4) {
        int s0 = __ldg(&d_csr_src[i + 0]);
        int s1 = __ldg(&d_csr_src[i + 1]);
        int s2 = __ldg(&d_csr_src[i + 2]);
        int s3 = __ldg(&d_csr_src[i + 3]);
        float w0 = __ldg(&d_csr_w[i + 0]);
        float w1 = __ldg(&d_csr_w[i + 1]);
        float w2 = __ldg(&d_csr_w[i + 2]);
        float w3 = __ldg(&d_csr_w[i + 3]);
        float2 v0 = nd[(size_t)s0 * 32 + lane];
        float2 v1 = nd[(size_t)s1 * 32 + lane];
        float2 v2 = nd[(size_t)s2 * 32 + lane];
        float2 v3 = nd[(size_t)s3 * 32 + lane];
        accx += v0.x * w0; accy += v0.y * w0;
        accx += v1.x * w1; accy += v1.y * w1;
        accx += v2.x * w2; accy += v2.y * w2;
        accx += v3.x * w3; accy += v3.y * w3;
    }
    for (; i < end; i++) {
        int s = __ldg(&d_csr_src[i]);
        float w = __ldg(&d_csr_w[i]);
        float2 v = nd[(size_t)s * 32 + lane];
        accx += v.x * w; accy += v.y * w;
    }
    reinterpret_cast<float2*>(d_agg)[(size_t)warp * 32 + lane] =
        make_float2(accx, accy);
}

// ---------------------------------------------------------------------------
__global__ void final_kernel(const float* __restrict__ Wr,
                             const float* __restrict__ br,
                             float* __restrict__ out) {
    __shared__ float sW[256];
    __shared__ float sb[4];
    if (threadIdx.x < 256) sW[threadIdx.x] = Wr[threadIdx.x];
    if (threadIdx.x < 4) sb[threadIdx.x] = br[threadIdx.x];
    __syncthreads();

    int r = blockIdx.x * blockDim.x + threadIdx.x;
    if (r >= Nn) return;
    const float4* inp = reinterpret_cast<const float4*>(d_node + (size_t)r * 64);
    float acc[4] = {sb[0], sb[1], sb[2], sb[3]};
#pragma unroll
    for (int k4 = 0; k4 < 16; k4++) {
        float4 x = inp[k4];
#pragma unroll
        for (int kk = 0; kk < 4; kk++) {
            float xk = (kk == 0) ? x.x : (kk == 1) ? x.y : (kk == 2) ? x.z : x.w;
            const float* wr = sW + (k4 * 4 + kk) * 4;
            acc[0] += xk * wr[0];
            acc[1] += xk * wr[1];
            acc[2] += xk * wr[2];
            acc[3] += xk * wr[3];
        }
    }
    reinterpret_cast<float4*>(out)[r] = make_float4(acc[0], acc[1], acc[2], acc[3]);
}

// ---------------------------------------------------------------------------
extern "C" void kernel_launch(void* const* d_in, const int* in_sizes, int n_in,
                              void* d_out, int out_size) {
    const float* x = (const float*)d_in[0];
    const int* ei = (const int*)d_in[1];
    const float* ea = (const float*)d_in[2];
    const float* Wn1 = (const float*)d_in[3];
    const float* bn1 = (const float*)d_in[4];
    const float* Wn2 = (const float*)d_in[5];
    const float* bn2 = (const float*)d_in[6];
    const float* We1 = (const float*)d_in[7];
    const float* be1 = (const float*)d_in[8];
    const float* We2 = (const float*)d_in[9];
    const float* be2 = (const float*)d_in[10];
    const float* Wg = (const float*)d_in[11];
    const float* bg = (const float*)d_in[12];
    const float* Wp1 = (const float*)d_in[13];
    const float* bp1 = (const float*)d_in[14];
    const float* Wp2 = (const float*)d_in[15];
    const float* bp2 = (const float*)d_in[16];
    const float* Wr = (const float*)d_in[17];
    const float* br = (const float*)d_in[18];

    const int NB = (Nn + 255) / 256;
    const int EB = (Ee + 255) / 256;
    const int GB = (Nn * 32 + 255) / 256;  // gather: warp per node

    // gcn_norm + CSR build
    init_kernel<<<NB, 256>>>();
    edge_kernel<<<EB, 256>>>((const float4*)ea, ei, We1, be1, We2, be2);
    dis_kernel<<<NB, 256>>>();
    norm_kernel<<<EB, 256>>>(ei);
    scan1_kernel<<<NTILES, SCAN_TILE>>>();
    scan2_kernel<<<1, 32>>>();
    scan3_kernel<<<NB, 256>>>();
    fill_kernel<<<EB, 256>>>(ei);

    // node MLP
    node1_kernel<<<NB, 256>>>(x, Wn1, bn1);
    gemm64_kernel<true><<<NB, 256>>>(Wn2, bn2, 0.2f);

    // 8 GCN layers: atomic-free CSR gather, then GEMM+bias+leaky
    for (int i = 0; i < 8; i++) {
        gather_kernel<<<GB, 256>>>();
        gemm64_kernel<true><<<NB, 256>>>(Wg + i * 4096, bg + i * 64, 0.2f);
    }

    // post MLP
    gemm64_kernel<false><<<NB, 256>>>(Wp1, bp1, 0.2f);
    gemm64_kernel<true><<<NB, 256>>>(Wp2, bp2, 0.2f);
    final_kernel<<<NB, 256>>>(Wr, br, (float*)d_out);
}

// round 3
// speedup vs baseline: 1.4819x; 1.0427x over previous
#include <cuda_runtime.h>
#include <math.h>

constexpr int Nn = 100000;
constexpr int Ee = 1600000;
constexpr int SCAN_TILE = 1024;
constexpr int NTILES = (Nn + SCAN_TILE - 1) / SCAN_TILE;  // 98

__device__ float d_node[Nn * 64];
__device__ float d_agg[Nn * 64];
__device__ float d_norm[Ee];       // raw edge weight (pre-norm)
__device__ float d_dis[Nn];        // degree -> deg^-0.5 (in place)
__device__ float d_selfnorm[Nn];   // dis[i]^2
__device__ int d_cnt[Nn];
__device__ int d_off[Nn + 1];
__device__ int d_cur[Nn];
__device__ int d_tile[NTILES];
__device__ int d_csr_src[Ee];
__device__ float d_csr_w[Ee];      // fully normalized weight

__device__ __forceinline__ float leaky(float v, float s) {
    return v > 0.0f ? v : s * v;
}

// ---------------------------------------------------------------------------
__global__ void init_kernel() {
    int i = blockIdx.x * blockDim.x + threadIdx.x;
    if (i < Nn) { d_dis[i] = 1.0f; d_cnt[i] = 0; }
}

// ---------------------------------------------------------------------------
// Edge MLP + degree accumulation + CSR count (fused).
__global__ void edge_kernel(const float4* __restrict__ ea,
                            const int* __restrict__ ei,
                            const float* __restrict__ W1,
                            const float* __restrict__ b1,
                            const float* __restrict__ W2,
                            const float* __restrict__ b2) {
    __shared__ float sW1[64];
    __shared__ float sb1[16];
    __shared__ float sW2[16];
    __shared__ float sb2;
    int t = threadIdx.x;
    if (t < 64) sW1[t] = W1[t];
    if (t < 16) sb1[t] = b1[t];
    if (t >= 64 && t < 80) sW2[t - 64] = W2[t - 64];
    if (t == 80) sb2 = b2[0];
    __syncthreads();

    int e = blockIdx.x * blockDim.x + t;
    if (e >= Ee) return;
    float4 a = ea[e];
    float a0 = isnan(a.x) ? 0.0f : a.x;
    float a1 = isnan(a.y) ? 0.0f : a.y;
    float a2 = isnan(a.z) ? 0.0f : a.z;
    float a3 = isnan(a.w) ? 0.0f : a.w;

    float s = sb2;
#pragma unroll
    for (int j = 0; j < 16; j++) {
        float v = a0 * sW1[j] + a1 * sW1[16 + j] + a2 * sW1[32 + j] +
                  a3 * sW1[48 + j] + sb1[j];
        v = leaky(v, 0.2f);
        s += v * sW2[j];
    }
    float ew = leaky(s, 0.005f);
    d_norm[e] = ew;
    int col = ei[Ee + e];
    atomicAdd(&d_dis[col], ew);
    atomicAdd(&d_cnt[col], 1);
}

// ---------------------------------------------------------------------------
__global__ void dis_kernel() {
    int i = blockIdx.x * blockDim.x + threadIdx.x;
    if (i >= Nn) return;
    float d = d_dis[i];
    float r = rsqrtf(d);
    if (isinf(r)) r = 0.0f;
    d_dis[i] = r;
    d_selfnorm[i] = r * r;
}

// ---------------------------------------------------------------------------
// 3-kernel exclusive scan of d_cnt -> d_off, d_cur.
__global__ void scan1_kernel() {
    __shared__ int sh[SCAN_TILE];
    int tid = threadIdx.x;
    int i = blockIdx.x * SCAN_TILE + tid;
    int v = (i < Nn) ? d_cnt[i] : 0;
    sh[tid] = v;
    __syncthreads();
#pragma unroll
    for (int s = 1; s < SCAN_TILE; s <<= 1) {
        int add = (tid >= s) ? sh[tid - s] : 0;
        __syncthreads();
        sh[tid] += add;
        __syncthreads();
    }
    if (i < Nn) d_off[i] = sh[tid];  // inclusive, tile-local (temp)
    if (tid == SCAN_TILE - 1) d_tile[blockIdx.x] = sh[tid];
}

__global__ void scan2_kernel() {
    if (threadIdx.x == 0 && blockIdx.x == 0) {
        int run = 0;
        for (int b = 0; b < NTILES; b++) {
            int s = d_tile[b];
            d_tile[b] = run;
            run += s;
        }
        d_off[Nn] = Ee;
    }
}

__global__ void scan3_kernel() {
    int i = blockIdx.x * blockDim.x + threadIdx.x;
    if (i >= Nn) return;
    int excl = d_off[i] - d_cnt[i] + d_tile[i / SCAN_TILE];
    d_off[i] = excl;
    d_cur[i] = excl;
}

// ---------------------------------------------------------------------------
// CSR fill + norm fusion: csr_w = dis[row] * ew * dis[col].
__global__ void fill_kernel(const int* __restrict__ ei) {
    int e = blockIdx.x * blockDim.x + threadIdx.x;
    if (e >= Ee) return;
    int row = ei[e];
    int col = ei[Ee + e];
    int pos = atomicAdd(&d_cur[col], 1);
    d_csr_src[pos] = row;
    d_csr_w[pos] = d_dis[row] * d_norm[e] * d_dis[col];
}

// ---------------------------------------------------------------------------
// Node MLP stage 1: x[N,7] -> leaky(@Wn1+bn1, 0.2) -> d_agg (as temp)
__global__ void node1_kernel(const float* __restrict__ x,
                             const float* __restrict__ W1,
                             const float* __restrict__ b1) {
    __shared__ float sW[7 * 64];
    __shared__ float sb[64];
    for (int i = threadIdx.x; i < 448; i += blockDim.x) sW[i] = W1[i];
    if (threadIdx.x < 64) sb[threadIdx.x] = b1[threadIdx.x];
    __syncthreads();

    int r = blockIdx.x * blockDim.x + threadIdx.x;
    if (r >= Nn) return;
    float xi[7];
#pragma unroll
    for (int i = 0; i < 7; i++) {
        float v = x[r * 7 + i];
        xi[i] = isnan(v) ? 0.0f : v;
    }
    float4* outp = reinterpret_cast<float4*>(d_agg) + (size_t)r * 16;
#pragma unroll
    for (int j4 = 0; j4 < 16; j4++) {
        float o[4];
#pragma unroll
        for (int c = 0; c < 4; c++) {
            int j = j4 * 4 + c;
            float v = sb[j];
#pragma unroll
            for (int i = 0; i < 7; i++) v += xi[i] * sW[i * 64 + j];
            o[c] = leaky(v, 0.2f);
        }
        outp[j4] = make_float4(o[0], o[1], o[2], o[3]);
    }
}

// ---------------------------------------------------------------------------
// 64x64 GEMM + bias + leaky using packed fma.rn.f32x2 (SASS FFMA2, 2x fp32
// FMA throughput; ptxas never emits it from plain C++). W fetched as
// ld.shared.v2.u64 (two packed pairs per LDS). Bit-exact fp32.
template <bool IN_AGG>
__global__ void __launch_bounds__(256) gemm64_kernel(const float* __restrict__ W,
                                                     const float* __restrict__ b,
                                                     float slope) {
    __shared__ float sW[4096];
    __shared__ float sb[64];
    {
        const float4* W4 = reinterpret_cast<const float4*>(W);
        float4* sW4 = reinterpret_cast<float4*>(sW);
        for (int i = threadIdx.x; i < 1024; i += 256) sW4[i] = W4[i];
        if (threadIdx.x < 64) sb[threadIdx.x] = b[threadIdx.x];
    }
    __syncthreads();

    int r = blockIdx.x * 256 + threadIdx.x;
    if (r >= Nn) return;

    const float* inbase = IN_AGG ? d_agg : d_node;
    const float4* inp = reinterpret_cast<const float4*>(inbase + (size_t)r * 64);

    unsigned long long acc[32];  // 32 packed f32x2 accumulators = 64 outputs
#pragma unroll
    for (int j = 0; j < 32; j++) {
        asm("mov.b64 %0, {%1, %2};"
            : "=l"(acc[j]) : "f"(sb[2 * j]), "f"(sb[2 * j + 1]));
    }

#pragma unroll 4
    for (int k4 = 0; k4 < 16; k4++) {
        float4 x = inp[k4];
#pragma unroll
        for (int kk = 0; kk < 4; kk++) {
            float xk = (kk == 0) ? x.x : (kk == 1) ? x.y : (kk == 2) ? x.z : x.w;
            unsigned long long xx;
            asm("mov.b64 %0, {%1, %1};" : "=l"(xx) : "f"(xk));
            const ulonglong2* wr = reinterpret_cast<const ulonglong2*>(
                sW + (k4 * 4 + kk) * 64);
#pragma unroll
            for (int j2 = 0; j2 < 16; j2++) {
                ulonglong2 wp = wr[j2];
                asm("fma.rn.f32x2 %0, %1, %2, %0;"
                    : "+l"(acc[2 * j2]) : "l"(xx), "l"(wp.x));
                asm("fma.rn.f32x2 %0, %1, %2, %0;"
                    : "+l"(acc[2 * j2 + 1]) : "l"(xx), "l"(wp.y));
            }
        }
    }

    float* outbase = IN_AGG ? d_node : d_agg;
    float4* outp = reinterpret_cast<float4*>(outbase + (size_t)r * 64);
#pragma unroll
    for (int j4 = 0; j4 < 16; j4++) {
        float o0, o1, o2, o3;
        asm("mov.b64 {%0, %1}, %2;" : "=f"(o0), "=f"(o1) : "l"(acc[2 * j4]));
        asm("mov.b64 {%0, %1}, %2;" : "=f"(o2), "=f"(o3) : "l"(acc[2 * j4 + 1]));
        outp[j4] = make_float4(leaky(o0, slope), leaky(o1, slope),
                               leaky(o2, slope), leaky(o3, slope));
    }
}

// ---------------------------------------------------------------------------
// CSR gather: one warp per destination node, float2 per lane (64 feats).
__global__ void __launch_bounds__(256) gather_kernel() {
    int warp = (blockIdx.x * blockDim.x + threadIdx.x) >> 5;
    if (warp >= Nn) return;
    int lane = threadIdx.x & 31;

    const float2* nd = reinterpret_cast<const float2*>(d_node);
    float sn = d_selfnorm[warp];
    float2 self = nd[(size_t)warp * 32 + lane];
    float accx = self.x * sn, accy = self.y * sn;

    int i = d_off[warp];
    int end = d_off[warp + 1];

    for (; i + 4 <= end; i += 4) {
        int s0 = __ldg(&d_csr_src[i + 0]);
        int s1 = __ldg(&d_csr_src[i + 1]);
        int s2 = __ldg(&d_csr_src[i + 2]);
        int s3 = __ldg(&d_csr_src[i + 3]);
        float w0 = __ldg(&d_csr_w[i + 0]);
        float w1 = __ldg(&d_csr_w[i + 1]);
        float w2 = __ldg(&d_csr_w[i + 2]);
        float w3 = __ldg(&d_csr_w[i + 3]);
        float2 v0 = nd[(size_t)s0 * 32 + lane];
        float2 v1 = nd[(size_t)s1 * 32 + lane];
        float2 v2 = nd[(size_t)s2 * 32 + lane];
        float2 v3 = nd[(size_t)s3 * 32 + lane];
        accx += v0.x * w0; accy += v0.y * w0;
        accx += v1.x * w1; accy += v1.y * w1;
        accx += v2.x * w2; accy += v2.y * w2;
        accx += v3.x * w3; accy += v3.y * w3;
    }
    for (; i < end; i++) {
        int s = __ldg(&d_csr_src[i]);
        float w = __ldg(&d_csr_w[i]);
        float2 v = nd[(size_t)s * 32 + lane];
        accx += v.x * w; accy += v.y * w;
    }
    reinterpret_cast<float2*>(d_agg)[(size_t)warp * 32 + lane] =
        make_float2(accx, accy);
}

// ---------------------------------------------------------------------------
__global__ void final_kernel(const float* __restrict__ Wr,
                             const float* __restrict__ br,
                             float* __restrict__ out) {
    __shared__ float sW[256];
    __shared__ float sb[4];
    if (threadIdx.x < 256) sW[threadIdx.x] = Wr[threadIdx.x];
    if (threadIdx.x < 4) sb[threadIdx.x] = br[threadIdx.x];
    __syncthreads();

    int r = blockIdx.x * blockDim.x + threadIdx.x;
    if (r >= Nn) return;
    const float4* inp = reinterpret_cast<const float4*>(d_node + (size_t)r * 64);
    float acc[4] = {sb[0], sb[1], sb[2], sb[3]};
#pragma unroll
    for (int k4 = 0; k4 < 16; k4++) {
        float4 x = inp[k4];
#pragma unroll
        for (int kk = 0; kk < 4; kk++) {
            float xk = (kk == 0) ? x.x : (kk == 1) ? x.y : (kk == 2) ? x.z : x.w;
            const float* wr = sW + (k4 * 4 + kk) * 4;
            acc[0] += xk * wr[0];
            acc[1] += xk * wr[1];
            acc[2] += xk * wr[2];
            acc[3] += xk * wr[3];
        }
    }
    reinterpret_cast<float4*>(out)[r] = make_float4(acc[0], acc[1], acc[2], acc[3]);
}

// ---------------------------------------------------------------------------
extern "C" void kernel_launch(void* const* d_in, const int* in_sizes, int n_in,
                              void* d_out, int out_size) {
    const float* x = (const float*)d_in[0];
    const int* ei = (const int*)d_in[1];
    const float* ea = (const float*)d_in[2];
    const float* Wn1 = (const float*)d_in[3];
    const float* bn1 = (const float*)d_in[4];
    const float* Wn2 = (const float*)d_in[5];
    const float* bn2 = (const float*)d_in[6];
    const float* We1 = (const float*)d_in[7];
    const float* be1 = (const float*)d_in[8];
    const float* We2 = (const float*)d_in[9];
    const float* be2 = (const float*)d_in[10];
    const float* Wg = (const float*)d_in[11];
    const float* bg = (const float*)d_in[12];
    const float* Wp1 = (const float*)d_in[13];
    const float* bp1 = (const float*)d_in[14];
    const float* Wp2 = (const float*)d_in[15];
    const float* bp2 = (const float*)d_in[16];
    const float* Wr = (const float*)d_in[17];
    const float* br = (const float*)d_in[18];

    const int NB = (Nn + 255) / 256;
    const int EB = (Ee + 255) / 256;
    const int GB = (Nn * 32 + 255) / 256;

    // gcn_norm + CSR build (norm fused into fill)
    init_kernel<<<NB, 256>>>();
    edge_kernel<<<EB, 256>>>((const float4*)ea, ei, We1, be1, We2, be2);
    dis_kernel<<<NB, 256>>>();
    scan1_kernel<<<NTILES, SCAN_TILE>>>();
    scan2_kernel<<<1, 32>>>();
    scan3_kernel<<<NB, 256>>>();
    fill_kernel<<<EB, 256>>>(ei);

    // node MLP
    node1_kernel<<<NB, 256>>>(x, Wn1, bn1);
    gemm64_kernel<true><<<NB, 256>>>(Wn2, bn2, 0.2f);

    // 8 GCN layers
    for (int i = 0; i < 8; i++) {
        gather_kernel<<<GB, 256>>>();
        gemm64_kernel<true><<<NB, 256>>>(Wg + i * 4096, bg + i * 64, 0.2f);
    }

    // post MLP
    gemm64_kernel<false><<<NB, 256>>>(Wp1, bp1, 0.2f);
    gemm64_kernel<true><<<NB, 256>>>(Wp2, bp2, 0.2f);
    final_kernel<<<NB, 256>>>(Wr, br, (float*)d_out);
}